// round 13
// baseline (speedup 1.0000x reference)
#include <cuda_runtime.h>
#include <cuda_fp16.h>
#include <cstdint>
#include <cstddef>

#define TOK 8192
#define DIN 4096
#define DOUT 4096
#define RANK 16
#define NBLK (DIN / 64)
#define K_EXT 4224            // DIN + 128 (16 lora + 1 bias + zero pad to BK mult)
#define SCALING 4.0f          // 16 / sqrt(16)

#define BM 128
#define BN 256
#define BK 128
#define NSTAGE 2
#define KITER (K_EXT / BK)    // 33

#define ROWB 272                             // 256B data + 16B pad; conflict-free ldmatrix
#define A_BYTES (BM * ROWB)                  // 34816
#define B_BYTES (BN * ROWB)                  // 69632
#define STAGE_BYTES (A_BYTES + B_BYTES)      // 104448
#define SMEM_TOTAL (NSTAGE * STAGE_BYTES)    // 208896 -> 1 CTA/SM

#define NT_TILES (DOUT / BN)                 // 16
#define MT_TILES (TOK / BM)                  // 64

#define NXU (TOK / 32)                       // 256 xu blocks (32 rows each)

// Extended operand buffers (static device scratch; no runtime allocation)
__device__ __align__(1024) __half g_A[(size_t)TOK * K_EXT];   // ~69 MB
__device__ __align__(1024) __half g_B[(size_t)DOUT * K_EXT];  // ~35 MB

__constant__ float c_nf4[16] = {
    -1.0f, -0.6961928009986877f, -0.5250730514526367f, -0.39491748809814453f,
    -0.28444138169288635f, -0.18477343022823334f, -0.09105003625154495f, 0.0f,
    0.07958029955625534f, 0.16093020141124725f, 0.24611230194568634f,
    0.33791524171829224f, 0.44070982933044434f, 0.5626170039176941f,
    0.7229568362236023f, 1.0f};

// ---------------------------------------------------------------- helpers
__device__ __forceinline__ uint32_t s2u(const void* p) {
    uint32_t a;
    asm("{ .reg .u64 t; cvta.to.shared.u64 t, %1; cvt.u32.u64 %0, t; }"
        : "=r"(a) : "l"(p));
    return a;
}
__device__ __forceinline__ void cp16(uint32_t s, const void* g) {
    asm volatile("cp.async.cg.shared.global [%0], [%1], 16;" :: "r"(s), "l"(g));
}
__device__ __forceinline__ void cp_commit() {
    asm volatile("cp.async.commit_group;" ::: "memory");
}
__device__ __forceinline__ void ldsm4(uint32_t addr, uint32_t& r0, uint32_t& r1,
                                      uint32_t& r2, uint32_t& r3) {
    asm volatile("ldmatrix.sync.aligned.m8n8.x4.shared.b16 {%0,%1,%2,%3}, [%4];"
                 : "=r"(r0), "=r"(r1), "=r"(r2), "=r"(r3) : "r"(addr));
}
__device__ __forceinline__ void mma16816(float* c, const uint32_t* a,
                                         const uint32_t* b) {
    asm volatile(
        "mma.sync.aligned.m16n8k16.row.col.f32.f16.f16.f32 "
        "{%0,%1,%2,%3}, {%4,%5,%6,%7}, {%8,%9}, {%0,%1,%2,%3};"
        : "+f"(c[0]), "+f"(c[1]), "+f"(c[2]), "+f"(c[3])
        : "r"(a[0]), "r"(a[1]), "r"(a[2]), "r"(a[3]), "r"(b[0]), "r"(b[1]));
}

// -------------------------------------------------------- fused prep kernel
// blocks [0, NXU): x -> fp16 g_A + u = x@lora_A (4 rows/warp, 32 rows/block).
// blocks [NXU, NXU + DOUT): NF4 dequant -> g_B (+ lora_B cols, bias, zeros)
__global__ void __launch_bounds__(256) prep_all(
    const float* __restrict__ x, const int* __restrict__ wc,
    const float* __restrict__ am, const float* __restrict__ bias,
    const float* __restrict__ la, const float* __restrict__ lb) {
    __shared__ float sA2[16][520];  // transposed lora_A chunk (~33 KB)
    int tid = threadIdx.x;
    int lane = tid & 31;

    if (blockIdx.x >= NXU) {
        // ---------------- prep_w path ----------------
        float lutv = c_nf4[lane & 15];
        int n = blockIdx.x - NXU;
        const int* wr = wc + (size_t)n * DIN;
        __half* br = g_B + (size_t)n * K_EXT;
        const float* amr = am + (size_t)n * NBLK;
        for (int k4 = tid; k4 < DIN / 4; k4 += 256) {
            int k = k4 * 4;
            int4 c = ((const int4*)wr)[k4];
            float s = amr[k >> 6];
            float v0 = __shfl_sync(0xffffffffu, lutv, c.x & 15);
            float v1 = __shfl_sync(0xffffffffu, lutv, c.y & 15);
            float v2 = __shfl_sync(0xffffffffu, lutv, c.z & 15);
            float v3 = __shfl_sync(0xffffffffu, lutv, c.w & 15);
            __half2 h0 = __floats2half2_rn(v0 * s, v1 * s);
            __half2 h1 = __floats2half2_rn(v2 * s, v3 * s);
            ((__half2*)br)[k4 * 2] = h0;
            ((__half2*)br)[k4 * 2 + 1] = h1;
        }
        // K-extension tail: 16 lora cols, bias col, zeros to K_EXT
        if (tid < RANK) br[DIN + tid] = __float2half(SCALING * lb[(size_t)tid * DOUT + n]);
        else if (tid == RANK) br[DIN + RANK] = __float2half(bias[n]);
        else if (tid < 128) br[DIN + tid] = __float2half(0.0f);
        return;
    }

    // ------------- prep_xu path: 32 rows/block, 4 rows per warp -------------
    int wid = tid >> 5;
    size_t m0 = (size_t)blockIdx.x * 32 + wid * 4;
    const float* xr[4];
    __half* ar[4];
#pragma unroll
    for (int r = 0; r < 4; r++) {
        xr[r] = x + (m0 + r) * DIN;
        ar[r] = g_A + (m0 + r) * K_EXT;
    }
    float acc[4][16];
#pragma unroll
    for (int r = 0; r < 4; r++)
#pragma unroll
        for (int q = 0; q < 16; q++) acc[r][q] = 0.0f;

    for (int kc = 0; kc < DIN; kc += 512) {
        __syncthreads();
        const float4* la4 = (const float4*)(la + (size_t)kc * 16);
        for (int i = tid; i < 2048; i += 256) {
            float4 v = la4[i];
            int kk = i >> 2, r0 = (i & 3) * 4;
            sA2[r0][kk] = v.x;
            sA2[r0 + 1][kk] = v.y;
            sA2[r0 + 2][kk] = v.z;
            sA2[r0 + 3][kk] = v.w;
        }
        __syncthreads();
#pragma unroll
        for (int ki = 0; ki < 4; ki++) {
            int k = ki * 128 + lane * 4;
            float xs[4][4];
#pragma unroll
            for (int r = 0; r < 4; r++) {
                float4 v = *(const float4*)(xr[r] + kc + k);
                xs[r][0] = v.x; xs[r][1] = v.y; xs[r][2] = v.z; xs[r][3] = v.w;
                __half2 h0 = __floats2half2_rn(v.x, v.y);
                __half2 h1 = __floats2half2_rn(v.z, v.w);
                uint2 st;
                st.x = *(uint32_t*)&h0;
                st.y = *(uint32_t*)&h1;
                *(uint2*)(ar[r] + kc + k) = st;
            }
#pragma unroll
            for (int q = 0; q < 16; q++) {
                float4 pv = *(const float4*)&sA2[q][k];
#pragma unroll
                for (int r = 0; r < 4; r++)
                    acc[r][q] += xs[r][0] * pv.x + xs[r][1] * pv.y +
                                 xs[r][2] * pv.z + xs[r][3] * pv.w;
            }
        }
    }
#pragma unroll
    for (int r = 0; r < 4; r++)
#pragma unroll
        for (int q = 0; q < 16; q++) {
            acc[r][q] += __shfl_xor_sync(0xffffffffu, acc[r][q], 16);
            acc[r][q] += __shfl_xor_sync(0xffffffffu, acc[r][q], 8);
            acc[r][q] += __shfl_xor_sync(0xffffffffu, acc[r][q], 4);
            acc[r][q] += __shfl_xor_sync(0xffffffffu, acc[r][q], 2);
            acc[r][q] += __shfl_xor_sync(0xffffffffu, acc[r][q], 1);
        }
#pragma unroll
    for (int r = 0; r < 4; r++) {
        if (lane == 0) {
#pragma unroll
            for (int q = 0; q < 16; q++) ar[r][DIN + q] = __float2half(acc[r][q]);
        }
        // tail: bias-one at DIN+16, zeros DIN+17 .. DIN+127
        ar[r][DIN + 16 + lane] = __float2half(lane == 0 ? 1.0f : 0.0f);
        if (lane < 16) ar[r][DIN + 48 + lane] = __float2half(0.0f);
        ar[r][DIN + 64 + lane] = __float2half(0.0f);
        ar[r][DIN + 96 + lane] = __float2half(0.0f);
    }
}

// -------------------------------------------------------- main GEMM
// out[TOK, DOUT] = A_ext @ B_extᵀ via mma.sync.m16n8k16 (fp16 in, fp32 acc).
// 256 threads = 8 warps (2x4 of 64x64 warptiles), BN=256, BK=128, 2 stages,
// 1 CTA/SM. Half the stage boundaries of BK=64 (33 vs 65); the per-boundary
// wait+bar.sync cost was the surviving bubble. Fill chunks for the next stage
// are issued during kh=0..5 so the wait_group 0 at kh=7 finds them landed.
__global__ void __launch_bounds__(256, 1) qlora_gemm(float* __restrict__ out) {
    extern __shared__ char smem[];
    uint32_t sb = s2u(smem);
    int tid = threadIdx.x, wid = tid >> 5, lane = tid & 31;
    int warp_m = wid & 1, warp_n = wid >> 1;   // 2 x 4

    // L2-banded CTA order: 8 m-tiles x 16 n-tiles per band (128 CTAs/band)
    int bid = (int)blockIdx.x;
    int band = bid >> 7;
    int local = bid & 127;
    int mt = band * 8 + (local & 7);   // 0..63
    int nt = local >> 3;               // 0..15

    // cp.async: 16 threads per row (16B each -> 256B row); 16 rows per pass.
    // A: 8 passes (128 rows), B: 16 passes (256 rows) -> 24 cp16/thread/stage.
    const __half* sA0 = g_A + (size_t)mt * BM * K_EXT +
                        (size_t)(tid >> 4) * K_EXT + (tid & 15) * 8;
    const __half* sB0 = g_B + (size_t)nt * BN * K_EXT +
                        (size_t)(tid >> 4) * K_EXT + (tid & 15) * 8;
    uint32_t dA0 = (uint32_t)(tid >> 4) * ROWB + (tid & 15) * 16;
    uint32_t dB0 = A_BYTES + dA0;

    uint32_t aLdBase = (warp_m * 64 + (lane & 15)) * ROWB + (lane >> 4) * 16;
    uint32_t bLdBase = A_BYTES +
        (warp_n * 64 + ((lane >> 4) & 1) * 8 + (lane & 7)) * ROWB +
        ((lane >> 3) & 1) * 16;

    float acc[4][8][4];
#pragma unroll
    for (int mi = 0; mi < 4; mi++)
#pragma unroll
        for (int ni = 0; ni < 8; ni++)
#pragma unroll
            for (int j = 0; j < 4; j++) acc[mi][ni][j] = 0.0f;

    // unified chunk index idx 0..23: idx<8 -> A pass idx; else B pass idx-8
#define ISSUE_ONE(base_, k0_, idx_)                                            \
    {                                                                          \
        if ((idx_) < 8)                                                        \
            cp16((base_) + dA0 + (idx_) * (16 * ROWB),                         \
                 sA0 + (k0_) + (size_t)(idx_) * 16 * K_EXT);                   \
        else                                                                   \
            cp16((base_) + dB0 + ((idx_) - 8) * (16 * ROWB),                   \
                 sB0 + (k0_) + (size_t)((idx_) - 8) * 16 * K_EXT);             \
    }

#define ISSUE_STAGE(stage, kiter)                                              \
    {                                                                          \
        uint32_t base_ = sb + (stage) * STAGE_BYTES;                           \
        int k0_ = (kiter) * BK;                                                \
        _Pragma("unroll")                                                      \
        for (int i = 0; i < 24; i++) ISSUE_ONE(base_, k0_, i);                 \
    }

    // Chunk ch (0..5): unified idx {4ch .. 4ch+3} = 4 cp16/thread
#define ISSUE_CHUNK(stage, kiter, ch)                                          \
    {                                                                          \
        uint32_t base_ = sb + (stage) * STAGE_BYTES;                           \
        int k0_ = (kiter) * BK;                                                \
        _Pragma("unroll")                                                      \
        for (int i = 4 * (ch); i < 4 * (ch) + 4; i++) ISSUE_ONE(base_, k0_, i);\
    }

#define LOAD_FRAGS(buf, aB, bB, kOff)                                          \
    {                                                                          \
        _Pragma("unroll")                                                      \
        for (int mi = 0; mi < 4; mi++)                                         \
            ldsm4((aB) + mi * (16 * ROWB) + (kOff),                            \
                  a[buf][mi][0], a[buf][mi][1], a[buf][mi][2], a[buf][mi][3]); \
        _Pragma("unroll")                                                      \
        for (int nj = 0; nj < 4; nj++)                                         \
            ldsm4((bB) + nj * (16 * ROWB) + (kOff),                            \
                  b[buf][2 * nj][0], b[buf][2 * nj][1],                        \
                  b[buf][2 * nj + 1][0], b[buf][2 * nj + 1][1]);               \
    }

    // Half an MMA block: mi in {h*2, h*2+1} -> 16 HMMA
#define MMA_HALF(buf, h)                                                       \
    {                                                                          \
        _Pragma("unroll")                                                      \
        for (int mi = 2 * (h); mi < 2 * (h) + 2; mi++)                         \
            _Pragma("unroll")                                                  \
            for (int ni = 0; ni < 8; ni++)                                     \
                mma16816(acc[mi][ni], a[buf][mi], b[buf][ni]);                 \
    }

    // ---- prologue: fill stage 0, preload iter-0 kh=0 fragments ----
    ISSUE_STAGE(0, 0); cp_commit();

    uint32_t a[2][4][4], b[2][8][2];
    asm volatile("cp.async.wait_group 0;" ::: "memory");
    __syncthreads();
    LOAD_FRAGS(0, sb + aLdBase, sb + bLdBase, 0);

    for (int it = 0; it < KITER; ++it) {
        int s = it & 1, sn = s ^ 1;
        uint32_t aB = sb + s * STAGE_BYTES + aLdBase;
        uint32_t bB = sb + s * STAGE_BYTES + bLdBase;
        bool pf = (it + 1 < KITER);

#pragma unroll
        for (int kh = 0; kh < 8; kh++) {      // eight k16 steps per BK=128
            int cur = kh & 1, nxb = cur ^ 1;
            if (kh < 7) {
                LOAD_FRAGS(nxb, aB, bB, (kh + 1) * 32);
                MMA_HALF(cur, 0);
                // next-stage fill chunk inside the tensor shadow (kh 0..5)
                if (pf && kh < 6) { ISSUE_CHUNK(sn, it + 1, kh); }
                MMA_HALF(cur, 1);
            } else {
                // rotated stage boundary under the final MMA block
                cp_commit();
                asm volatile("cp.async.wait_group 0;" ::: "memory");
                __syncthreads();
                if (pf) {
                    uint32_t aB2 = sb + sn * STAGE_BYTES + aLdBase;
                    uint32_t bB2 = sb + sn * STAGE_BYTES + bLdBase;
                    LOAD_FRAGS(nxb, aB2, bB2, 0);   // nxb == 0 here
                }
                MMA_HALF(cur, 0);
                MMA_HALF(cur, 1);
            }
        }
    }

    // ---- epilogue: registers -> global fp32 ----
    int m0 = mt * BM + warp_m * 64 + (lane >> 2);
    int n0 = nt * BN + warp_n * 64 + (lane & 3) * 2;
#pragma unroll
    for (int mi = 0; mi < 4; mi++) {
#pragma unroll
        for (int ni = 0; ni < 8; ni++) {
            float* p0 = out + (size_t)(m0 + mi * 16) * DOUT + n0 + ni * 8;
            float* p1 = p0 + 8 * DOUT;
            *(float2*)p0 = make_float2(acc[mi][ni][0], acc[mi][ni][1]);
            *(float2*)p1 = make_float2(acc[mi][ni][2], acc[mi][ni][3]);
        }
    }
}

// -------------------------------------------------------- launch
extern "C" void kernel_launch(void* const* d_in, const int* in_sizes, int n_in,
                              void* d_out, int out_size) {
    const float* x = (const float*)d_in[0];
    const int* wc = (const int*)d_in[1];
    const float* am = (const float*)d_in[2];
    const float* bias = (const float*)d_in[3];
    const float* la = (const float*)d_in[4];
    const float* lb = (const float*)d_in[5];
    float* out = (float*)d_out;

    cudaFuncSetAttribute(qlora_gemm, cudaFuncAttributeMaxDynamicSharedMemorySize,
                         SMEM_TOTAL);

    prep_all<<<NXU + DOUT, 256>>>(x, wc, am, bias, la, lb);
    qlora_gemm<<<MT_TILES * NT_TILES, 256, SMEM_TOTAL>>>(out);
}

// round 14
// speedup vs baseline: 1.0650x; 1.0650x over previous
#include <cuda_runtime.h>
#include <cuda_fp16.h>
#include <cstdint>
#include <cstddef>

#define TOK 8192
#define DIN 4096
#define DOUT 4096
#define RANK 16
#define NBLK (DIN / 64)
#define K_EXT 4160            // DIN + 64 (16 lora cols + 1 bias col + pad)
#define SCALING 4.0f          // 16 / sqrt(16)

#define BM 128
#define BN 128
#define BK 64
#define NSTAGE 3
#define KITER (K_EXT / BK)    // 65

#define ROWB 144                             // 128B data + 16B pad; conflict-free ldmatrix
#define A_BYTES (BM * ROWB)                  // 18432
#define B_BYTES (BN * ROWB)                  // 18432
#define STAGE_BYTES (A_BYTES + B_BYTES)      // 36864
#define SMEM_TOTAL (NSTAGE * STAGE_BYTES)    // 110592 -> 2 CTAs/SM

#define NT_TILES (DOUT / BN)                 // 32
#define MT_TILES (TOK / BM)                  // 64

#define NXU (TOK / 32)                       // 256 xu blocks (32 rows each)

// Extended operand buffers (static device scratch; no runtime allocation)
__device__ __align__(1024) __half g_A[(size_t)TOK * K_EXT];   // ~68 MB
__device__ __align__(1024) __half g_B[(size_t)DOUT * K_EXT];  // ~34 MB

__constant__ float c_nf4[16] = {
    -1.0f, -0.6961928009986877f, -0.5250730514526367f, -0.39491748809814453f,
    -0.28444138169288635f, -0.18477343022823334f, -0.09105003625154495f, 0.0f,
    0.07958029955625534f, 0.16093020141124725f, 0.24611230194568634f,
    0.33791524171829224f, 0.44070982933044434f, 0.5626170039176941f,
    0.7229568362236023f, 1.0f};

// ---------------------------------------------------------------- helpers
__device__ __forceinline__ uint32_t s2u(const void* p) {
    uint32_t a;
    asm("{ .reg .u64 t; cvta.to.shared.u64 t, %1; cvt.u32.u64 %0, t; }"
        : "=r"(a) : "l"(p));
    return a;
}
__device__ __forceinline__ void cp16(uint32_t s, const void* g) {
    asm volatile("cp.async.cg.shared.global [%0], [%1], 16;" :: "r"(s), "l"(g));
}
__device__ __forceinline__ void cp_commit() {
    asm volatile("cp.async.commit_group;" ::: "memory");
}
__device__ __forceinline__ void ldsm4(uint32_t addr, uint32_t& r0, uint32_t& r1,
                                      uint32_t& r2, uint32_t& r3) {
    asm volatile("ldmatrix.sync.aligned.m8n8.x4.shared.b16 {%0,%1,%2,%3}, [%4];"
                 : "=r"(r0), "=r"(r1), "=r"(r2), "=r"(r3) : "r"(addr));
}
__device__ __forceinline__ void mma16816(float* c, const uint32_t* a,
                                         const uint32_t* b) {
    asm volatile(
        "mma.sync.aligned.m16n8k16.row.col.f32.f16.f16.f32 "
        "{%0,%1,%2,%3}, {%4,%5,%6,%7}, {%8,%9}, {%0,%1,%2,%3};"
        : "+f"(c[0]), "+f"(c[1]), "+f"(c[2]), "+f"(c[3])
        : "r"(a[0]), "r"(a[1]), "r"(a[2]), "r"(a[3]), "r"(b[0]), "r"(b[1]));
}

// -------------------------------------------------------- fused prep kernel
// blocks [0, NXU): x -> fp16 g_A + u = x@lora_A (4 rows/warp, 32 rows/block).
//   Launched FIRST so the long xu blocks overlap the w blocks' wave.
// blocks [NXU, NXU + DOUT): NF4 dequant -> g_B (+ lora_B cols, bias, zeros)
__global__ void __launch_bounds__(256) prep_all(
    const float* __restrict__ x, const int* __restrict__ wc,
    const float* __restrict__ am, const float* __restrict__ bias,
    const float* __restrict__ la, const float* __restrict__ lb) {
    __shared__ float sA2[16][520];  // transposed lora_A chunk (~33 KB)
    int tid = threadIdx.x;
    int lane = tid & 31;

    if (blockIdx.x >= NXU) {
        // ---------------- prep_w path ----------------
        // All 4 code loads + 4 scale loads hoisted (MLP=4+ against DRAM
        // latency; this path is latency-bound, not BW-bound). Codebook
        // lookup stays a single shfl.idx (no const-cache divergent replay).
        float lutv = c_nf4[lane & 15];
        int n = blockIdx.x - NXU;
        const int* wr = wc + (size_t)n * DIN;
        __half* br = g_B + (size_t)n * K_EXT;
        const float* amr = am + (size_t)n * NBLK;

        int4 c[4];
        float s[4];
#pragma unroll
        for (int i = 0; i < 4; i++) {
            int k4 = tid + i * 256;
            c[i] = ((const int4*)wr)[k4];
            s[i] = amr[(k4 * 4) >> 6];
        }
#pragma unroll
        for (int i = 0; i < 4; i++) {
            int k4 = tid + i * 256;
            float v0 = __shfl_sync(0xffffffffu, lutv, c[i].x & 15);
            float v1 = __shfl_sync(0xffffffffu, lutv, c[i].y & 15);
            float v2 = __shfl_sync(0xffffffffu, lutv, c[i].z & 15);
            float v3 = __shfl_sync(0xffffffffu, lutv, c[i].w & 15);
            __half2 h0 = __floats2half2_rn(v0 * s[i], v1 * s[i]);
            __half2 h1 = __floats2half2_rn(v2 * s[i], v3 * s[i]);
            ((__half2*)br)[k4 * 2] = h0;
            ((__half2*)br)[k4 * 2 + 1] = h1;
        }
        if (tid < RANK) br[DIN + tid] = __float2half(SCALING * lb[(size_t)tid * DOUT + n]);
        else if (tid == RANK) br[DIN + RANK] = __float2half(bias[n]);
        else if (tid < 64) br[DIN + tid] = __float2half(0.0f);
        return;
    }

    // ------------- prep_xu path: 32 rows/block, 4 rows per warp -------------
    int wid = tid >> 5;
    size_t m0 = (size_t)blockIdx.x * 32 + wid * 4;
    const float* xr[4];
    __half* ar[4];
#pragma unroll
    for (int r = 0; r < 4; r++) {
        xr[r] = x + (m0 + r) * DIN;
        ar[r] = g_A + (m0 + r) * K_EXT;
    }
    float acc[4][16];
#pragma unroll
    for (int r = 0; r < 4; r++)
#pragma unroll
        for (int q = 0; q < 16; q++) acc[r][q] = 0.0f;

    for (int kc = 0; kc < DIN; kc += 512) {
        __syncthreads();
        const float4* la4 = (const float4*)(la + (size_t)kc * 16);
        for (int i = tid; i < 2048; i += 256) {
            float4 v = la4[i];
            int kk = i >> 2, r0 = (i & 3) * 4;
            sA2[r0][kk] = v.x;
            sA2[r0 + 1][kk] = v.y;
            sA2[r0 + 2][kk] = v.z;
            sA2[r0 + 3][kk] = v.w;
        }
        __syncthreads();
#pragma unroll
        for (int ki = 0; ki < 4; ki++) {     // 4 quads of 128 k per 512-chunk
            int k = ki * 128 + lane * 4;
            float xs[4][4];
#pragma unroll
            for (int r = 0; r < 4; r++) {
                float4 v = *(const float4*)(xr[r] + kc + k);
                xs[r][0] = v.x; xs[r][1] = v.y; xs[r][2] = v.z; xs[r][3] = v.w;
                __half2 h0 = __floats2half2_rn(v.x, v.y);
                __half2 h1 = __floats2half2_rn(v.z, v.w);
                uint2 st;
                st.x = *(uint32_t*)&h0;
                st.y = *(uint32_t*)&h1;
                *(uint2*)(ar[r] + kc + k) = st;
            }
#pragma unroll
            for (int q = 0; q < 16; q++) {
                float4 pv = *(const float4*)&sA2[q][k];
#pragma unroll
                for (int r = 0; r < 4; r++)
                    acc[r][q] += xs[r][0] * pv.x + xs[r][1] * pv.y +
                                 xs[r][2] * pv.z + xs[r][3] * pv.w;
            }
        }
    }
#pragma unroll
    for (int r = 0; r < 4; r++)
#pragma unroll
        for (int q = 0; q < 16; q++) {
            acc[r][q] += __shfl_xor_sync(0xffffffffu, acc[r][q], 16);
            acc[r][q] += __shfl_xor_sync(0xffffffffu, acc[r][q], 8);
            acc[r][q] += __shfl_xor_sync(0xffffffffu, acc[r][q], 4);
            acc[r][q] += __shfl_xor_sync(0xffffffffu, acc[r][q], 2);
            acc[r][q] += __shfl_xor_sync(0xffffffffu, acc[r][q], 1);
        }
#pragma unroll
    for (int r = 0; r < 4; r++) {
        if (lane == 0) {
#pragma unroll
            for (int q = 0; q < 16; q++) ar[r][DIN + q] = __float2half(acc[r][q]);
        }
        ar[r][DIN + 16 + lane] = __float2half(lane == 0 ? 1.0f : 0.0f);
        if (lane < 16) ar[r][DIN + 48 + lane] = __float2half(0.0f);
    }
}

// -------------------------------------------------------- main GEMM
// out[TOK, DOUT] = A_ext @ B_extᵀ via mma.sync.m16n8k16 (fp16 in, fp32 acc).
// Best-measured config (R11): 128 threads = 4 warps (2x2 of 64x64 warptiles),
// 2 CTAs/SM, BK=64, 3 stages. Rotated pipeline: the stage-boundary
// wait_group+syncthreads sits before the LAST MMA block, with next-stage kh=0
// fragments preloaded there; cp.async chunks issued between MMA halves.
__global__ void __launch_bounds__(128, 2) qlora_gemm(float* __restrict__ out) {
    extern __shared__ char smem[];
    uint32_t sb = s2u(smem);
    int tid = threadIdx.x, wid = tid >> 5, lane = tid & 31;
    int warp_m = wid & 1, warp_n = wid >> 1;   // 2 x 2

    // L2-banded CTA order: 8 m-tiles x 32 n-tiles per band (256 CTAs/band)
    int bid = (int)blockIdx.x;
    int band = bid >> 8;
    int local = bid & 255;
    int mt = band * 8 + (local & 7);   // 0..63
    int nt = local >> 3;               // 0..31

    // cp.async: 128 threads, 8 x 16B chunks per row-group of 16 rows
    const __half* sA0 = g_A + (size_t)mt * BM * K_EXT +
                        (size_t)(tid >> 3) * K_EXT + (tid & 7) * 8;
    const __half* sB0 = g_B + (size_t)nt * BN * K_EXT +
                        (size_t)(tid >> 3) * K_EXT + (tid & 7) * 8;
    uint32_t dA0 = (uint32_t)(tid >> 3) * ROWB + (tid & 7) * 16;
    uint32_t dB0 = A_BYTES + dA0;

    uint32_t aLdBase = (warp_m * 64 + (lane & 15)) * ROWB + (lane >> 4) * 16;
    uint32_t bLdBase = A_BYTES +
        (warp_n * 64 + ((lane >> 4) & 1) * 8 + (lane & 7)) * ROWB +
        ((lane >> 3) & 1) * 16;

    float acc[4][8][4];
#pragma unroll
    for (int mi = 0; mi < 4; mi++)
#pragma unroll
        for (int ni = 0; ni < 8; ni++)
#pragma unroll
            for (int j = 0; j < 4; j++) acc[mi][ni][j] = 0.0f;

#define ISSUE_STAGE(stage, kiter)                                              \
    {                                                                          \
        uint32_t base_ = sb + (stage) * STAGE_BYTES;                           \
        int k0_ = (kiter) * BK;                                                \
        _Pragma("unroll")                                                      \
        for (int i = 0; i < 8; i++)                                            \
            cp16(base_ + dA0 + i * (16 * ROWB),                                \
                 sA0 + k0_ + (size_t)i * 16 * K_EXT);                          \
        _Pragma("unroll")                                                      \
        for (int i = 0; i < 8; i++)                                            \
            cp16(base_ + dB0 + i * (16 * ROWB),                                \
                 sB0 + k0_ + (size_t)i * 16 * K_EXT);                          \
    }

    // Chunk ch (0..3): A row-groups {2ch, 2ch+1} + B row-groups {2ch, 2ch+1}
#define ISSUE_CHUNK(stage, kiter, ch)                                          \
    {                                                                          \
        uint32_t base_ = sb + (stage) * STAGE_BYTES;                           \
        int k0_ = (kiter) * BK;                                                \
        _Pragma("unroll")                                                      \
        for (int i = 2 * (ch); i < 2 * (ch) + 2; i++) {                        \
            cp16(base_ + dA0 + i * (16 * ROWB),                                \
                 sA0 + k0_ + (size_t)i * 16 * K_EXT);                          \
            cp16(base_ + dB0 + i * (16 * ROWB),                                \
                 sB0 + k0_ + (size_t)i * 16 * K_EXT);                          \
        }                                                                      \
    }

#define LOAD_FRAGS(buf, aB, bB, kOff)                                          \
    {                                                                          \
        _Pragma("unroll")                                                      \
        for (int mi = 0; mi < 4; mi++)                                         \
            ldsm4((aB) + mi * (16 * ROWB) + (kOff),                            \
                  a[buf][mi][0], a[buf][mi][1], a[buf][mi][2], a[buf][mi][3]); \
        _Pragma("unroll")                                                      \
        for (int nj = 0; nj < 4; nj++)                                         \
            ldsm4((bB) + nj * (16 * ROWB) + (kOff),                            \
                  b[buf][2 * nj][0], b[buf][2 * nj][1],                        \
                  b[buf][2 * nj + 1][0], b[buf][2 * nj + 1][1]);               \
    }

    // Half an MMA block: mi in {h*2, h*2+1} -> 16 HMMA
#define MMA_HALF(buf, h)                                                       \
    {                                                                          \
        _Pragma("unroll")                                                      \
        for (int mi = 2 * (h); mi < 2 * (h) + 2; mi++)                         \
            _Pragma("unroll")                                                  \
            for (int ni = 0; ni < 8; ni++)                                     \
                mma16816(acc[mi][ni], a[buf][mi], b[buf][ni]);                 \
    }

    // ---- prologue: fill 2 stages, preload iter-0 kh=0 fragments ----
    ISSUE_STAGE(0, 0); cp_commit();
    ISSUE_STAGE(1, 1); cp_commit();

    uint32_t a[2][4][4], b[2][8][2];
    asm volatile("cp.async.wait_group %0;" :: "n"(1) : "memory");
    __syncthreads();
    LOAD_FRAGS(0, sb + aLdBase, sb + bLdBase, 0);

    int s = 0, sn = 2;
    for (int it = 0; it < KITER; ++it) {
        uint32_t aB = sb + s * STAGE_BYTES + aLdBase;
        uint32_t bB = sb + s * STAGE_BYTES + bLdBase;
        bool pf = (it + 2 < KITER);

#pragma unroll
        for (int kh = 0; kh < 4; kh++) {      // four k16 steps per BK=64
            int cur = kh & 1, nxb = cur ^ 1;
            if (kh < 3) {
                LOAD_FRAGS(nxb, aB, bB, (kh + 1) * 32);
                MMA_HALF(cur, 0);
                // cp chunk issued inside the tensor shadow, between MMA halves
                if (pf) { ISSUE_CHUNK(sn, it + 2, kh); }
                MMA_HALF(cur, 1);
            } else {
                // rotated stage boundary: sync + next-stage kh=0 preload are
                // hidden under the final MMA block below
                if (pf) { ISSUE_CHUNK(sn, it + 2, 3); }
                cp_commit();
                asm volatile("cp.async.wait_group %0;" :: "n"(1) : "memory");
                __syncthreads();
                if (it + 1 < KITER) {
                    int s1 = (s == 2) ? 0 : s + 1;
                    uint32_t aB2 = sb + s1 * STAGE_BYTES + aLdBase;
                    uint32_t bB2 = sb + s1 * STAGE_BYTES + bLdBase;
                    LOAD_FRAGS(nxb, aB2, bB2, 0);   // nxb == 0 here
                }
                MMA_HALF(cur, 0);
                MMA_HALF(cur, 1);
            }
        }

        s = (s == 2) ? 0 : s + 1;
        sn = (sn == 2) ? 0 : sn + 1;
    }

    // ---- epilogue: registers -> global fp32 ----
    int m0 = mt * BM + warp_m * 64 + (lane >> 2);
    int n0 = nt * BN + warp_n * 64 + (lane & 3) * 2;
#pragma unroll
    for (int mi = 0; mi < 4; mi++) {
#pragma unroll
        for (int ni = 0; ni < 8; ni++) {
            float* p0 = out + (size_t)(m0 + mi * 16) * DOUT + n0 + ni * 8;
            float* p1 = p0 + 8 * DOUT;
            *(float2*)p0 = make_float2(acc[mi][ni][0], acc[mi][ni][1]);
            *(float2*)p1 = make_float2(acc[mi][ni][2], acc[mi][ni][3]);
        }
    }
}

// -------------------------------------------------------- launch
extern "C" void kernel_launch(void* const* d_in, const int* in_sizes, int n_in,
                              void* d_out, int out_size) {
    const float* x = (const float*)d_in[0];
    const int* wc = (const int*)d_in[1];
    const float* am = (const float*)d_in[2];
    const float* bias = (const float*)d_in[3];
    const float* la = (const float*)d_in[4];
    const float* lb = (const float*)d_in[5];
    float* out = (float*)d_out;

    cudaFuncSetAttribute(qlora_gemm, cudaFuncAttributeMaxDynamicSharedMemorySize,
                         SMEM_TOTAL);

    prep_all<<<NXU + DOUT, 256>>>(x, wc, am, bias, la, lb);
    qlora_gemm<<<MT_TILES * NT_TILES, 128, SMEM_TOTAL>>>(out);
}